// round 1
// baseline (speedup 1.0000x reference)
#include <cuda_runtime.h>
#include <cuda_bf16.h>
#include <math.h>

// Problem constants
#define BB 8
#define SS 2048
#define DD 1024

// Scratch (allocation-free rule: __device__ globals)
__device__ float g_Q[BB * SS * DD];
__device__ float g_K[BB * SS * DD];
__device__ float g_V[BB * SS * DD];
__device__ float g_CTX[BB * SS * DD];

// ---------------------------------------------------------------------------
// Classic tiled SGEMM: C = alpha * A @ B
// A: [M,K] row-major, B: [K,N] row-major, C: [M,N] row-major.
// BM=BN=128, BK=8, 256 threads, 8x8 per thread. All dims assumed multiples
// of the tile sizes (true for this problem: 16384/2048/1024 all % 128 == 0,
// K % 8 == 0).
// blockIdx.z = batch, with element strides sA/sB/sC.
// ---------------------------------------------------------------------------
__global__ __launch_bounds__(256)
void sgemm_nn(const float* __restrict__ A, const float* __restrict__ B,
              float* __restrict__ C, int M, int N, int K,
              long long sA, long long sB, long long sC, float alpha)
{
    __shared__ float As[8][128];
    __shared__ float Bs[8][128];

    const int tid = threadIdx.x;
    A += (long long)blockIdx.z * sA + (long long)blockIdx.y * 128 * K;
    B += (long long)blockIdx.z * sB + (long long)blockIdx.x * 128;
    C += (long long)blockIdx.z * sC + (long long)blockIdx.y * 128 * N
         + (long long)blockIdx.x * 128;

    // A tile loader: 128 rows x 8 cols -> one float4 per thread
    const int aRow = tid >> 1;
    const int aCol = (tid & 1) * 4;
    // B tile loader: 8 rows x 128 cols -> one float4 per thread
    const int bRow = tid >> 5;
    const int bCol = (tid & 31) * 4;

    const int trow = (tid >> 4) * 8;   // 16x16 thread grid over 128x128
    const int tcol = (tid & 15) * 8;

    float acc[8][8];
    #pragma unroll
    for (int i = 0; i < 8; i++)
        #pragma unroll
        for (int j = 0; j < 8; j++) acc[i][j] = 0.f;

    for (int k0 = 0; k0 < K; k0 += 8) {
        float4 a4 = *reinterpret_cast<const float4*>(A + (long long)aRow * K + k0 + aCol);
        As[aCol + 0][aRow] = a4.x;
        As[aCol + 1][aRow] = a4.y;
        As[aCol + 2][aRow] = a4.z;
        As[aCol + 3][aRow] = a4.w;
        float4 b4 = *reinterpret_cast<const float4*>(B + (long long)(k0 + bRow) * N + bCol);
        *reinterpret_cast<float4*>(&Bs[bRow][bCol]) = b4;
        __syncthreads();

        #pragma unroll
        for (int kk = 0; kk < 8; kk++) {
            float ar[8], br[8];
            #pragma unroll
            for (int i = 0; i < 8; i++) ar[i] = As[kk][trow + i];
            #pragma unroll
            for (int j = 0; j < 8; j++) br[j] = Bs[kk][tcol + j];
            #pragma unroll
            for (int i = 0; i < 8; i++)
                #pragma unroll
                for (int j = 0; j < 8; j++)
                    acc[i][j] = fmaf(ar[i], br[j], acc[i][j]);
        }
        __syncthreads();
    }

    #pragma unroll
    for (int i = 0; i < 8; i++) {
        float4 o0 = make_float4(acc[i][0] * alpha, acc[i][1] * alpha,
                                acc[i][2] * alpha, acc[i][3] * alpha);
        float4 o1 = make_float4(acc[i][4] * alpha, acc[i][5] * alpha,
                                acc[i][6] * alpha, acc[i][7] * alpha);
        float* cp = C + (long long)(trow + i) * N + tcol;
        *reinterpret_cast<float4*>(cp)     = o0;
        *reinterpret_cast<float4*>(cp + 4) = o1;
    }
}

// ---------------------------------------------------------------------------
// SGEMM NT: C = alpha * A @ B^T.  A: [M,K] rm, B: [N,K] rm, C: [M,N] rm.
// Used for scores = Q @ K^T.
// ---------------------------------------------------------------------------
__global__ __launch_bounds__(256)
void sgemm_nt(const float* __restrict__ A, const float* __restrict__ B,
              float* __restrict__ C, int M, int N, int K,
              long long sA, long long sB, long long sC, float alpha)
{
    __shared__ float As[8][128];
    __shared__ float Bs[8][128];

    const int tid = threadIdx.x;
    A += (long long)blockIdx.z * sA + (long long)blockIdx.y * 128 * K;
    B += (long long)blockIdx.z * sB + (long long)blockIdx.x * 128 * K;
    C += (long long)blockIdx.z * sC + (long long)blockIdx.y * 128 * N
         + (long long)blockIdx.x * 128;

    const int aRow = tid >> 1;
    const int aCol = (tid & 1) * 4;
    // B tile: 128 rows (n) x 8 cols (k), float4 along k, transposed store
    const int bN = tid >> 1;
    const int bK = (tid & 1) * 4;

    const int trow = (tid >> 4) * 8;
    const int tcol = (tid & 15) * 8;

    float acc[8][8];
    #pragma unroll
    for (int i = 0; i < 8; i++)
        #pragma unroll
        for (int j = 0; j < 8; j++) acc[i][j] = 0.f;

    for (int k0 = 0; k0 < K; k0 += 8) {
        float4 a4 = *reinterpret_cast<const float4*>(A + (long long)aRow * K + k0 + aCol);
        As[aCol + 0][aRow] = a4.x;
        As[aCol + 1][aRow] = a4.y;
        As[aCol + 2][aRow] = a4.z;
        As[aCol + 3][aRow] = a4.w;
        float4 b4 = *reinterpret_cast<const float4*>(B + (long long)bN * K + k0 + bK);
        Bs[bK + 0][bN] = b4.x;
        Bs[bK + 1][bN] = b4.y;
        Bs[bK + 2][bN] = b4.z;
        Bs[bK + 3][bN] = b4.w;
        __syncthreads();

        #pragma unroll
        for (int kk = 0; kk < 8; kk++) {
            float ar[8], br[8];
            #pragma unroll
            for (int i = 0; i < 8; i++) ar[i] = As[kk][trow + i];
            #pragma unroll
            for (int j = 0; j < 8; j++) br[j] = Bs[kk][tcol + j];
            #pragma unroll
            for (int i = 0; i < 8; i++)
                #pragma unroll
                for (int j = 0; j < 8; j++)
                    acc[i][j] = fmaf(ar[i], br[j], acc[i][j]);
        }
        __syncthreads();
    }

    #pragma unroll
    for (int i = 0; i < 8; i++) {
        float4 o0 = make_float4(acc[i][0] * alpha, acc[i][1] * alpha,
                                acc[i][2] * alpha, acc[i][3] * alpha);
        float4 o1 = make_float4(acc[i][4] * alpha, acc[i][5] * alpha,
                                acc[i][6] * alpha, acc[i][7] * alpha);
        float* cp = C + (long long)(trow + i) * N + tcol;
        *reinterpret_cast<float4*>(cp)     = o0;
        *reinterpret_cast<float4*>(cp + 4) = o1;
    }
}

// ---------------------------------------------------------------------------
// Row softmax in place. One block per row; 256 threads; cols = 2048.
// ---------------------------------------------------------------------------
__inline__ __device__ float warpMax(float v) {
    #pragma unroll
    for (int o = 16; o > 0; o >>= 1) v = fmaxf(v, __shfl_xor_sync(0xffffffffu, v, o));
    return v;
}
__inline__ __device__ float warpSum(float v) {
    #pragma unroll
    for (int o = 16; o > 0; o >>= 1) v += __shfl_xor_sync(0xffffffffu, v, o);
    return v;
}

__global__ __launch_bounds__(256)
void softmax_rows(float* __restrict__ W)
{
    float* row = W + (long long)blockIdx.x * SS;
    const int tid = threadIdx.x;
    __shared__ float red[8];

    float v[8];
    float m = -INFINITY;
    #pragma unroll
    for (int i = 0; i < 8; i++) {
        v[i] = row[tid + i * 256];
        m = fmaxf(m, v[i]);
    }
    m = warpMax(m);
    if ((tid & 31) == 0) red[tid >> 5] = m;
    __syncthreads();
    if (tid < 32) {
        float t = (tid < 8) ? red[tid] : -INFINITY;
        t = warpMax(t);
        if (tid == 0) red[0] = t;
    }
    __syncthreads();
    m = red[0];

    float s = 0.f;
    #pragma unroll
    for (int i = 0; i < 8; i++) {
        v[i] = __expf(v[i] - m);
        s += v[i];
    }
    s = warpSum(s);
    __syncthreads();
    if ((tid & 31) == 0) red[tid >> 5] = s;
    __syncthreads();
    if (tid < 32) {
        float t = (tid < 8) ? red[tid] : 0.f;
        t = warpSum(t);
        if (tid == 0) red[0] = t;
    }
    __syncthreads();
    const float inv = 1.0f / red[0];

    #pragma unroll
    for (int i = 0; i < 8; i++) row[tid + i * 256] = v[i] * inv;
}

// ---------------------------------------------------------------------------
// kernel_launch
// d_in: 0=input [B,S,D], 1=context [B,S,D], 2=Wq, 3=Wk, 4=Wv, 5=Wo (all [D,D])
// d_out: output [B,S,D] followed by weights [B,S,S], fp32.
// ---------------------------------------------------------------------------
extern "C" void kernel_launch(void* const* d_in, const int* in_sizes, int n_in,
                              void* d_out, int out_size)
{
    const float* input   = (const float*)d_in[0];
    const float* context = (const float*)d_in[1];
    const float* Wq      = (const float*)d_in[2];
    const float* Wk      = (const float*)d_in[3];
    const float* Wv      = (const float*)d_in[4];
    const float* Wo      = (const float*)d_in[5];

    float* out     = (float*)d_out;                          // [B,S,D]
    float* weights = out + (long long)BB * SS * DD;          // [B,S,S]

    float *qp, *kp, *vp, *cp;
    cudaGetSymbolAddress((void**)&qp, g_Q);
    cudaGetSymbolAddress((void**)&kp, g_K);
    cudaGetSymbolAddress((void**)&vp, g_V);
    cudaGetSymbolAddress((void**)&cp, g_CTX);

    const dim3 blk(256);
    const long long SD = (long long)SS * DD;
    const long long SSq = (long long)SS * SS;

    // 1) Projections: [B*S, D] @ [D, D]
    {
        dim3 g(DD / 128, (BB * SS) / 128, 1);
        sgemm_nn<<<g, blk>>>(input,   Wq, qp, BB * SS, DD, DD, 0, 0, 0, 1.0f);
        sgemm_nn<<<g, blk>>>(context, Wk, kp, BB * SS, DD, DD, 0, 0, 0, 1.0f);
        sgemm_nn<<<g, blk>>>(context, Wv, vp, BB * SS, DD, DD, 0, 0, 0, 1.0f);
    }

    // 2) scores = Q @ K^T * (1/sqrt(D)), per batch, into weights slice
    {
        dim3 g(SS / 128, SS / 128, BB);
        sgemm_nt<<<g, blk>>>(qp, kp, weights, SS, SS, DD, SD, SD, SSq, 0.03125f);
    }

    // 3) softmax in place over last dim
    softmax_rows<<<BB * SS, blk>>>(weights);

    // 4) ctx = weights @ V, per batch
    {
        dim3 g(DD / 128, SS / 128, BB);
        sgemm_nn<<<g, blk>>>(weights, vp, cp, SS, DD, SS, SSq, SD, SD, 1.0f);
    }

    // 5) output = ctx @ Wo : [B*S, D] @ [D, D]
    {
        dim3 g(DD / 128, (BB * SS) / 128, 1);
        sgemm_nn<<<g, blk>>>(cp, Wo, out, BB * SS, DD, DD, 0, 0, 0, 1.0f);
    }
}

// round 4
// speedup vs baseline: 6.1345x; 6.1345x over previous
#include <cuda_runtime.h>
#include <cuda_bf16.h>
#include <math.h>
#include <stdint.h>

// Problem constants
#define BB 8
#define SS 2048
#define DD 1024

// Tiles
#define BM 128
#define BN 256
#define BK 32   // fp32 elements per K-chunk (= 128 bytes = one SW128 row)

// tcgen05 only exists in the arch-specific (sm_103a) compilation pass.
#if defined(__CUDA_ARCH_FEAT_SM103_ALL) || defined(__CUDA_ARCH_FEAT_SM100_ALL) || \
    (defined(__CUDA_ARCH_SPECIFIC__) && (__CUDA_ARCH__ >= 1000))
#define HAS_TCGEN05 1
#else
#define HAS_TCGEN05 0
#endif

// Scratch (allocation-free rule: __device__ globals)
__device__ float g_Q[BB * SS * DD];
__device__ float g_K[BB * SS * DD];
__device__ float g_V[BB * SS * DD];
__device__ float g_VT[BB * SS * DD];          // V^T per batch: [B, D, S]
__device__ float g_CTX[BB * SS * DD];
__device__ float g_WT[4][DD * DD];            // WqT, WkT, WvT, WoT

// ---------------------------------------------------------------------------
// PTX helpers
// ---------------------------------------------------------------------------
__device__ __forceinline__ uint32_t smem_u32(const void* p) {
    uint32_t a;
    asm("{ .reg .u64 t; cvta.to.shared.u64 t, %1; cvt.u32.u64 %0, t; }" : "=r"(a) : "l"(p));
    return a;
}

#if HAS_TCGEN05
__device__ __forceinline__ uint32_t elect_one() {
    uint32_t pred;
    asm volatile("{\n\t.reg .pred p;\n\telect.sync _|p, 0xFFFFFFFF;\n\tselp.b32 %0, 1, 0, p;\n\t}" : "=r"(pred));
    return pred;
}
#define MBAR_INIT(addr, cnt) \
    asm volatile("mbarrier.init.shared.b64 [%0], %1;" :: "r"(addr), "r"(cnt) : "memory")
#define MBAR_WAIT(addr, par) do {                                              \
    uint32_t _m = (addr), _p = (par), _d;                                      \
    asm volatile("{\n\t.reg .pred p;\n\t"                                      \
        "mbarrier.try_wait.parity.acquire.cta.shared::cta.b64 p, [%1], %2;\n\t"\
        "selp.b32 %0, 1, 0, p;\n\t}" : "=r"(_d) : "r"(_m), "r"(_p) : "memory");\
    if (!_d) {                                                                 \
        asm volatile("{\n\t.reg .pred P1;\n\t"                                 \
        "W_%=:\n\t"                                                            \
        "mbarrier.try_wait.parity.acquire.cta.shared::cta.b64 P1, [%0], %1, 0x989680;\n\t" \
        "@P1 bra.uni D_%=;\n\tbra.uni W_%=;\n\tD_%=:\n\t}"                     \
        :: "r"(_m), "r"(_p) : "memory");                                       \
    }                                                                          \
} while (0)

#define TCG_ALLOC(smem_addr, n) \
    asm volatile("tcgen05.alloc.cta_group::1.sync.aligned.shared::cta.b32 [%0], %1;" :: "r"(smem_addr), "r"(n) : "memory")
#define TCG_RELINQ() \
    asm volatile("tcgen05.relinquish_alloc_permit.cta_group::1.sync.aligned;")
#define TCG_DEALLOC(tmem, n) \
    asm volatile("tcgen05.dealloc.cta_group::1.sync.aligned.b32 %0, %1;" :: "r"(tmem), "r"(n))
#define TCG_COMMIT(mbar) \
    asm volatile("tcgen05.commit.cta_group::1.mbarrier::arrive::one.shared::cluster.b64 [%0];" :: "r"(mbar) : "memory")
#define TCG_FENCE_BEFORE() asm volatile("tcgen05.fence::before_thread_sync;" ::: "memory")
#define TCG_FENCE_AFTER()  asm volatile("tcgen05.fence::after_thread_sync;" ::: "memory")
#define TCG_WAIT_LD()      asm volatile("tcgen05.wait::ld.sync.aligned;" ::: "memory")
#define FENCE_ASYNC_SHARED() asm volatile("fence.proxy.async.shared::cta;" ::: "memory")

#define TCG_LD_X32(r, tmem)                                                    \
    asm volatile("tcgen05.ld.sync.aligned.32x32b.x32.b32 "                     \
        "{%0, %1, %2, %3, %4, %5, %6, %7, %8, %9, %10, %11, %12, %13, %14, %15, " \
        " %16, %17, %18, %19, %20, %21, %22, %23, %24, %25, %26, %27, %28, %29, %30, %31}, [%32];" \
        : "=r"((r)[0]),  "=r"((r)[1]),  "=r"((r)[2]),  "=r"((r)[3]),           \
          "=r"((r)[4]),  "=r"((r)[5]),  "=r"((r)[6]),  "=r"((r)[7]),           \
          "=r"((r)[8]),  "=r"((r)[9]),  "=r"((r)[10]), "=r"((r)[11]),          \
          "=r"((r)[12]), "=r"((r)[13]), "=r"((r)[14]), "=r"((r)[15]),          \
          "=r"((r)[16]), "=r"((r)[17]), "=r"((r)[18]), "=r"((r)[19]),          \
          "=r"((r)[20]), "=r"((r)[21]), "=r"((r)[22]), "=r"((r)[23]),          \
          "=r"((r)[24]), "=r"((r)[25]), "=r"((r)[26]), "=r"((r)[27]),          \
          "=r"((r)[28]), "=r"((r)[29]), "=r"((r)[30]), "=r"((r)[31])           \
        : "r"(tmem))

// SW128 K-major SMEM descriptor (layout 2, version 1, LBO=1, SBO=64)
__device__ __forceinline__ uint64_t make_desc(uint32_t addr) {
    const uint64_t base = (uint64_t(2) << 61) | (uint64_t(1) << 46)
                        | (uint64_t(64) << 32) | (uint64_t(1) << 16);
    return base | ((uint64_t)(addr >> 4) & 0x3FFF);
}

// idesc: dtype=F32(1)<<4, atype=TF32(2)<<7, btype=TF32(2)<<10,
//        N>>3 (=32) <<17, M>>4 (=8) <<24
#define IDESC_TF32 ((1u << 4) | (2u << 7) | (2u << 10) | ((BN / 8) << 17) | ((BM / 16) << 24))

__device__ __forceinline__ void mma_tf32_ss(uint32_t d_tmem, uint64_t a_desc,
                                            uint64_t b_desc, uint32_t enable) {
    asm volatile(
        "{\n\t.reg .pred p;\n\t"
        "setp.ne.u32 p, %4, 0;\n\t"
        "tcgen05.mma.cta_group::1.kind::tf32 [%0], %1, %2, %3, {%5, %5, %5, %5}, p;\n\t}"
        :: "r"(d_tmem), "l"(a_desc), "l"(b_desc), "r"(IDESC_TF32),
           "r"(enable), "r"(0u)
        : "memory");
}
#endif // HAS_TCGEN05

__device__ __forceinline__ uint32_t swz(uint32_t off) {   // SW128 swizzle
    return off ^ ((off >> 3) & 0x70);
}
__device__ __forceinline__ uint32_t f2tf32(float f) {
    uint32_t u;
    asm("cvt.rna.tf32.f32 %0, %1;" : "=r"(u) : "f"(f));
    return u;
}

// SMEM layout (dynamic): [0]=tmem ptr, [16],[24]=mbar0/1, tiles 1024-aligned
#define SM_TMEMPTR 0
#define SM_MBAR0   16
#define SM_MBAR1   24
#define SM_A0      1024
#define SM_A1      (SM_A0 + BM * 128)            // 17408
#define SM_B0      (SM_A1 + BM * 128)            // 33792
#define SM_B1      (SM_B0 + BN * 128)            // 66560
#define SM_TOTAL   (SM_B1 + BN * 128)            // 99328

// ---------------------------------------------------------------------------
// Generic NT GEMM:  C[m][n] = alpha * sum_k A[m][k] * B[n][k]
// A: [M,K] rm (rows by*128), B: [N,K] rm (rows bx*256), C: [M, ldc] rm.
// K multiple of 32, per-batch strides via blockIdx.z.
// sm_103a pass: tcgen05 tf32. Baseline pass: FFMA fallback (never selected
// at runtime on sm_103a hardware; fatbin arch resolution prefers the exact
// sm_103a SASS).
// ---------------------------------------------------------------------------
__global__ void __launch_bounds__(256)
gemm_nt_tf32(const float* __restrict__ A, const float* __restrict__ B,
             float* __restrict__ C, int K, int ldc,
             long long sA, long long sB, long long sC, float alpha)
{
    const int tid = threadIdx.x;

    A += (long long)blockIdx.z * sA + (long long)blockIdx.y * BM * K;
    B += (long long)blockIdx.z * sB + (long long)blockIdx.x * BN * K;
    C += (long long)blockIdx.z * sC + (long long)blockIdx.y * BM * ldc
         + (long long)blockIdx.x * BN;

#if HAS_TCGEN05
    extern __shared__ char smem[];
    const uint32_t sbase = smem_u32(smem);
    const int wid = tid >> 5;
    const int lid = tid & 31;

    // TMEM alloc (warp 0) + mbarrier init (thread 0)
    if (wid == 0) {
        TCG_ALLOC(sbase + SM_TMEMPTR, 256);
        TCG_RELINQ();
    }
    if (tid == 0) {
        MBAR_INIT(sbase + SM_MBAR0, 1);
        MBAR_INIT(sbase + SM_MBAR1, 1);
    }
    __syncthreads();
    uint32_t tmem;
    asm volatile("ld.shared.b32 %0, [%1];" : "=r"(tmem) : "r"(sbase + SM_TMEMPTR));

    const int KT = K / BK;
    // loader coords: 8 lanes per row (8 x float4 = 128B), rows step by 32
    const int lrow = tid >> 3;
    const int lcol = (tid & 7) * 16;   // byte offset within 128B row

    for (int ic = 0; ic < KT; ic++) {
        const int buf = ic & 1;
        const int use = ic >> 1;
        const uint32_t mbar = sbase + (buf ? SM_MBAR1 : SM_MBAR0);
        if (use > 0) { MBAR_WAIT(mbar, (use - 1) & 1); }

        const uint32_t aBase = sbase + (buf ? SM_A1 : SM_A0);
        const uint32_t bBase = sbase + (buf ? SM_B1 : SM_B0);
        const long long k0 = (long long)ic * BK;

        // A chunk: 128 rows x 32 floats
        #pragma unroll
        for (int p = 0; p < BM / 32; p++) {
            const int r = lrow + p * 32;
            const float4 v = *reinterpret_cast<const float4*>(A + (long long)r * K + k0 + (lcol >> 2));
            uint32_t d0 = f2tf32(v.x), d1 = f2tf32(v.y), d2 = f2tf32(v.z), d3 = f2tf32(v.w);
            const uint32_t a = aBase + swz((uint32_t)(r * 128 + lcol));
            asm volatile("st.shared.v4.b32 [%0], {%1,%2,%3,%4};"
                         :: "r"(a), "r"(d0), "r"(d1), "r"(d2), "r"(d3) : "memory");
        }
        // B chunk: 256 rows x 32 floats
        #pragma unroll
        for (int p = 0; p < BN / 32; p++) {
            const int r = lrow + p * 32;
            const float4 v = *reinterpret_cast<const float4*>(B + (long long)r * K + k0 + (lcol >> 2));
            uint32_t d0 = f2tf32(v.x), d1 = f2tf32(v.y), d2 = f2tf32(v.z), d3 = f2tf32(v.w);
            const uint32_t a = bBase + swz((uint32_t)(r * 128 + lcol));
            asm volatile("st.shared.v4.b32 [%0], {%1,%2,%3,%4};"
                         :: "r"(a), "r"(d0), "r"(d1), "r"(d2), "r"(d3) : "memory");
        }
        FENCE_ASYNC_SHARED();
        __syncthreads();

        if (wid == 0) {
            if (elect_one()) {
                const uint64_t ad = make_desc(aBase);
                const uint64_t bd = make_desc(bBase);
                #pragma unroll
                for (int s = 0; s < 4; s++) {   // 4 x K=8 tf32 steps per 128B row
                    mma_tf32_ss(tmem, ad + s * 2, bd + s * 2,
                                (ic > 0 || s > 0) ? 1u : 0u);
                }
                TCG_COMMIT(mbar);
            }
        }
    }

    // wait for the final commit (in-order per CTA => all MMAs done)
    {
        const int lastBuf = (KT - 1) & 1;
        const int cnt = (KT + 1) >> 1;           // completions on lastBuf
        const uint32_t mbar = sbase + (lastBuf ? SM_MBAR1 : SM_MBAR0);
        MBAR_WAIT(mbar, (cnt - 1) & 1);
    }
    TCG_FENCE_AFTER();

    // Epilogue: 8 warps; rows (wid&3)*32+lid, col half (wid>>2)*128
    {
        const int m = (wid & 3) * 32 + lid;
        const int chalf = (wid >> 2) * 128;
        float* crow = C + (long long)m * ldc + chalf;
        #pragma unroll
        for (int j = 0; j < 4; j++) {
            uint32_t r[32];
            TCG_LD_X32(r, tmem + chalf + j * 32);
            TCG_WAIT_LD();
            float f[32];
            #pragma unroll
            for (int c = 0; c < 32; c++) f[c] = __uint_as_float(r[c]) * alpha;
            #pragma unroll
            for (int c = 0; c < 8; c++)
                *reinterpret_cast<float4*>(crow + j * 32 + c * 4) =
                    *reinterpret_cast<float4*>(&f[c * 4]);
        }
    }
    TCG_FENCE_BEFORE();
    __syncthreads();
    if (wid == 0) TCG_DEALLOC(tmem, 256);

#else
    // Baseline-pass fallback (plain FFMA, correct but slow; not expected to
    // be selected at runtime). Each thread: 8 rows x 16 cols micro-tile.
    const int trow = (tid >> 4) * 8;         // 16x16 grid over 128x256
    const int tcol = (tid & 15) * 16;
    float acc[8][16];
    #pragma unroll
    for (int i = 0; i < 8; i++)
        #pragma unroll
        for (int j = 0; j < 16; j++) acc[i][j] = 0.f;
    for (int k = 0; k < K; k++) {
        float ar[8], br[16];
        #pragma unroll
        for (int i = 0; i < 8; i++)
            ar[i] = __uint_as_float(f2tf32(A[(long long)(trow + i) * K + k]));
        #pragma unroll
        for (int j = 0; j < 16; j++)
            br[j] = __uint_as_float(f2tf32(B[(long long)(tcol + j) * K + k]));
        #pragma unroll
        for (int i = 0; i < 8; i++)
            #pragma unroll
            for (int j = 0; j < 16; j++)
                acc[i][j] = fmaf(ar[i], br[j], acc[i][j]);
    }
    #pragma unroll
    for (int i = 0; i < 8; i++)
        #pragma unroll
        for (int j = 0; j < 16; j++)
            C[(long long)(trow + i) * ldc + tcol + j] = acc[i][j] * alpha;
#endif
}

// ---------------------------------------------------------------------------
// Tiled transpose: out[c][r] = in[r][c].  R, C multiples of 32.
// ---------------------------------------------------------------------------
__global__ void __launch_bounds__(256)
transpose_k(const float* __restrict__ in, float* __restrict__ out,
            int R, int C, long long sIn, long long sOut)
{
    __shared__ float t[32][33];
    in  += (long long)blockIdx.z * sIn;
    out += (long long)blockIdx.z * sOut;
    const int c0 = blockIdx.x * 32, r0 = blockIdx.y * 32;
    #pragma unroll
    for (int i = threadIdx.y; i < 32; i += 8)
        t[i][threadIdx.x] = in[(long long)(r0 + i) * C + c0 + threadIdx.x];
    __syncthreads();
    #pragma unroll
    for (int i = threadIdx.y; i < 32; i += 8)
        out[(long long)(c0 + i) * R + r0 + threadIdx.x] = t[threadIdx.x][i];
}

// ---------------------------------------------------------------------------
// Row softmax in place. One block per row; 256 threads; cols = 2048.
// ---------------------------------------------------------------------------
__inline__ __device__ float warpMax(float v) {
    #pragma unroll
    for (int o = 16; o > 0; o >>= 1) v = fmaxf(v, __shfl_xor_sync(0xffffffffu, v, o));
    return v;
}
__inline__ __device__ float warpSum(float v) {
    #pragma unroll
    for (int o = 16; o > 0; o >>= 1) v += __shfl_xor_sync(0xffffffffu, v, o);
    return v;
}

__global__ void __launch_bounds__(256)
softmax_rows(float* __restrict__ W)
{
    float* row = W + (long long)blockIdx.x * SS;
    const int tid = threadIdx.x;
    __shared__ float red[8];

    float v[8];
    float m = -INFINITY;
    #pragma unroll
    for (int i = 0; i < 8; i++) {
        v[i] = row[tid + i * 256];
        m = fmaxf(m, v[i]);
    }
    m = warpMax(m);
    if ((tid & 31) == 0) red[tid >> 5] = m;
    __syncthreads();
    if (tid < 32) {
        float t = (tid < 8) ? red[tid] : -INFINITY;
        t = warpMax(t);
        if (tid == 0) red[0] = t;
    }
    __syncthreads();
    m = red[0];

    float s = 0.f;
    #pragma unroll
    for (int i = 0; i < 8; i++) {
        v[i] = __expf(v[i] - m);
        s += v[i];
    }
    s = warpSum(s);
    __syncthreads();
    if ((tid & 31) == 0) red[tid >> 5] = s;
    __syncthreads();
    if (tid < 32) {
        float t = (tid < 8) ? red[tid] : 0.f;
        t = warpSum(t);
        if (tid == 0) red[0] = t;
    }
    __syncthreads();
    const float inv = 1.0f / red[0];

    #pragma unroll
    for (int i = 0; i < 8; i++) row[tid + i * 256] = v[i] * inv;
}

// ---------------------------------------------------------------------------
// kernel_launch
// d_in: 0=input [B,S,D], 1=context [B,S,D], 2=Wq, 3=Wk, 4=Wv, 5=Wo ([D,D])
// d_out: output [B,S,D] then weights [B,S,S], fp32.
// ---------------------------------------------------------------------------
extern "C" void kernel_launch(void* const* d_in, const int* in_sizes, int n_in,
                              void* d_out, int out_size)
{
    const float* input   = (const float*)d_in[0];
    const float* context = (const float*)d_in[1];
    const float* Wq      = (const float*)d_in[2];
    const float* Wk      = (const float*)d_in[3];
    const float* Wv      = (const float*)d_in[4];
    const float* Wo      = (const float*)d_in[5];

    float* out     = (float*)d_out;                          // [B,S,D]
    float* weights = out + (long long)BB * SS * DD;          // [B,S,S]

    float *qp, *kp, *vp, *vtp, *cp, *wtp;
    cudaGetSymbolAddress((void**)&qp,  g_Q);
    cudaGetSymbolAddress((void**)&kp,  g_K);
    cudaGetSymbolAddress((void**)&vp,  g_V);
    cudaGetSymbolAddress((void**)&vtp, g_VT);
    cudaGetSymbolAddress((void**)&cp,  g_CTX);
    cudaGetSymbolAddress((void**)&wtp, g_WT);
    float* WqT = wtp;
    float* WkT = wtp + 1 * DD * DD;
    float* WvT = wtp + 2 * DD * DD;
    float* WoT = wtp + 3 * DD * DD;

    cudaFuncSetAttribute(gemm_nt_tf32,
                         cudaFuncAttributeMaxDynamicSharedMemorySize, SM_TOTAL);

    const dim3 blk(256);
    const dim3 tblk(32, 8);
    const long long SD  = (long long)SS * DD;
    const long long SSq = (long long)SS * SS;

    // 0) Transpose weight matrices: [D,D] -> [D,D]^T
    {
        dim3 g(DD / 32, DD / 32, 1);
        transpose_k<<<g, tblk>>>(Wq, WqT, DD, DD, 0, 0);
        transpose_k<<<g, tblk>>>(Wk, WkT, DD, DD, 0, 0);
        transpose_k<<<g, tblk>>>(Wv, WvT, DD, DD, 0, 0);
        transpose_k<<<g, tblk>>>(Wo, WoT, DD, DD, 0, 0);
    }

    // 1) Projections: [B*S, D] @ W  == NT with W^T as B operand
    {
        dim3 g(DD / BN, (BB * SS) / BM, 1);
        gemm_nt_tf32<<<g, blk, SM_TOTAL>>>(input,   WqT, qp, DD, DD, 0, 0, 0, 1.0f);
        gemm_nt_tf32<<<g, blk, SM_TOTAL>>>(context, WkT, kp, DD, DD, 0, 0, 0, 1.0f);
        gemm_nt_tf32<<<g, blk, SM_TOTAL>>>(context, WvT, vp, DD, DD, 0, 0, 0, 1.0f);
    }

    // 1b) V^T per batch: [S,D] -> [D,S]
    {
        dim3 g(DD / 32, SS / 32, BB);
        transpose_k<<<g, tblk>>>(vp, vtp, SS, DD, SD, SD);
    }

    // 2) scores = Q @ K^T * (1/sqrt(D)) -> weights slice (native NT)
    {
        dim3 g(SS / BN, SS / BM, BB);
        gemm_nt_tf32<<<g, blk, SM_TOTAL>>>(qp, kp, weights, DD, SS, SD, SD, SSq, 0.03125f);
    }

    // 3) softmax in place over last dim
    softmax_rows<<<BB * SS, blk>>>(weights);

    // 4) ctx = weights @ V  == NT with V^T rows as B operand
    {
        dim3 g(DD / BN, SS / BM, BB);
        gemm_nt_tf32<<<g, blk, SM_TOTAL>>>(weights, vtp, cp, SS, DD, SSq, SD, SD, 1.0f);
    }

    // 5) output = ctx @ Wo == NT with Wo^T
    {
        dim3 g(DD / BN, (BB * SS) / BM, 1);
        gemm_nt_tf32<<<g, blk, SM_TOTAL>>>(cp, WoT, out, DD, DD, 0, 0, 0, 1.0f);
    }
}

// round 6
// speedup vs baseline: 9.9488x; 1.6218x over previous
#include <cuda_runtime.h>
#include <cuda_fp16.h>
#include <math.h>
#include <stdint.h>

// Problem constants
#define BB 8
#define SS 2048
#define DD 1024

// Tiles (fp16): one SW128 row = 128 bytes = 64 fp16 K-elements
#define BM 128
#define BN 256
#define BK 64

// tcgen05 only exists in the arch-specific (sm_103a) compilation pass.
#if defined(__CUDA_ARCH_FEAT_SM103_ALL) || defined(__CUDA_ARCH_FEAT_SM100_ALL) || \
    (defined(__CUDA_ARCH_SPECIFIC__) && (__CUDA_ARCH__ >= 1000))
#define HAS_TCGEN05 1
#else
#define HAS_TCGEN05 0
#endif

// Scratch (allocation-free rule: __device__ globals), all fp16 operands
__device__ __half g_XH[BB * SS * DD];         // input fp16
__device__ __half g_CH[BB * SS * DD];         // context fp16
__device__ __half g_WTH[4][DD * DD];          // WqT,WkT,WvT,WoT fp16
__device__ __half g_QH[BB * SS * DD];
__device__ __half g_KH[BB * SS * DD];
__device__ __half g_VH[BB * SS * DD];
__device__ __half g_VTH[BB * SS * DD];        // V^T per batch [B, D, S]
__device__ __half g_WH[(long long)BB * SS * SS];  // softmax weights fp16 copy
__device__ __half g_CTXH[BB * SS * DD];

// ---------------------------------------------------------------------------
// PTX helpers
// ---------------------------------------------------------------------------
__device__ __forceinline__ uint32_t smem_u32(const void* p) {
    uint32_t a;
    asm("{ .reg .u64 t; cvta.to.shared.u64 t, %1; cvt.u32.u64 %0, t; }" : "=r"(a) : "l"(p));
    return a;
}

#if HAS_TCGEN05
__device__ __forceinline__ uint32_t elect_one() {
    uint32_t pred;
    asm volatile("{\n\t.reg .pred p;\n\telect.sync _|p, 0xFFFFFFFF;\n\tselp.b32 %0, 1, 0, p;\n\t}" : "=r"(pred));
    return pred;
}
#define MBAR_INIT(addr, cnt) \
    asm volatile("mbarrier.init.shared.b64 [%0], %1;" :: "r"(addr), "r"(cnt) : "memory")
#define MBAR_WAIT(addr, par) do {                                              \
    uint32_t _m = (addr), _p = (par), _d;                                      \
    asm volatile("{\n\t.reg .pred p;\n\t"                                      \
        "mbarrier.try_wait.parity.acquire.cta.shared::cta.b64 p, [%1], %2;\n\t"\
        "selp.b32 %0, 1, 0, p;\n\t}" : "=r"(_d) : "r"(_m), "r"(_p) : "memory");\
    if (!_d) {                                                                 \
        asm volatile("{\n\t.reg .pred P1;\n\t"                                 \
        "W_%=:\n\t"                                                            \
        "mbarrier.try_wait.parity.acquire.cta.shared::cta.b64 P1, [%0], %1, 0x989680;\n\t" \
        "@P1 bra.uni D_%=;\n\tbra.uni W_%=;\n\tD_%=:\n\t}"                     \
        :: "r"(_m), "r"(_p) : "memory");                                       \
    }                                                                          \
} while (0)

#define TCG_ALLOC(smem_addr, n) \
    asm volatile("tcgen05.alloc.cta_group::1.sync.aligned.shared::cta.b32 [%0], %1;" :: "r"(smem_addr), "r"(n) : "memory")
#define TCG_RELINQ() \
    asm volatile("tcgen05.relinquish_alloc_permit.cta_group::1.sync.aligned;")
#define TCG_DEALLOC(tmem, n) \
    asm volatile("tcgen05.dealloc.cta_group::1.sync.aligned.b32 %0, %1;" :: "r"(tmem), "r"(n))
#define TCG_COMMIT(mbar) \
    asm volatile("tcgen05.commit.cta_group::1.mbarrier::arrive::one.shared::cluster.b64 [%0];" :: "r"(mbar) : "memory")
#define TCG_FENCE_BEFORE() asm volatile("tcgen05.fence::before_thread_sync;" ::: "memory")
#define TCG_FENCE_AFTER()  asm volatile("tcgen05.fence::after_thread_sync;" ::: "memory")
#define TCG_WAIT_LD()      asm volatile("tcgen05.wait::ld.sync.aligned;" ::: "memory")
#define FENCE_ASYNC_SHARED() asm volatile("fence.proxy.async.shared::cta;" ::: "memory")

#define TCG_LD_X32(r, tmem)                                                    \
    asm volatile("tcgen05.ld.sync.aligned.32x32b.x32.b32 "                     \
        "{%0, %1, %2, %3, %4, %5, %6, %7, %8, %9, %10, %11, %12, %13, %14, %15, " \
        " %16, %17, %18, %19, %20, %21, %22, %23, %24, %25, %26, %27, %28, %29, %30, %31}, [%32];" \
        : "=r"((r)[0]),  "=r"((r)[1]),  "=r"((r)[2]),  "=r"((r)[3]),           \
          "=r"((r)[4]),  "=r"((r)[5]),  "=r"((r)[6]),  "=r"((r)[7]),           \
          "=r"((r)[8]),  "=r"((r)[9]),  "=r"((r)[10]), "=r"((r)[11]),          \
          "=r"((r)[12]), "=r"((r)[13]), "=r"((r)[14]), "=r"((r)[15]),          \
          "=r"((r)[16]), "=r"((r)[17]), "=r"((r)[18]), "=r"((r)[19]),          \
          "=r"((r)[20]), "=r"((r)[21]), "=r"((r)[22]), "=r"((r)[23]),          \
          "=r"((r)[24]), "=r"((r)[25]), "=r"((r)[26]), "=r"((r)[27]),          \
          "=r"((r)[28]), "=r"((r)[29]), "=r"((r)[30]), "=r"((r)[31])           \
        : "r"(tmem))

// SW128 K-major SMEM descriptor (layout 2, version 1, LBO=1, SBO=64)
__device__ __forceinline__ uint64_t make_desc(uint32_t addr) {
    const uint64_t base = (uint64_t(2) << 61) | (uint64_t(1) << 46)
                        | (uint64_t(64) << 32) | (uint64_t(1) << 16);
    return base | ((uint64_t)(addr >> 4) & 0x3FFF);
}

// idesc kind::f16, fp16 inputs, fp32 accum:
//   dtype=F32(1)<<4, atype=FP16(0)<<7, btype=FP16(0)<<10,
//   N>>3 <<17, M>>4 <<24
#define IDESC_F16 ((1u << 4) | ((BN / 8) << 17) | ((BM / 16) << 24))

__device__ __forceinline__ void mma_f16_ss(uint32_t d_tmem, uint64_t a_desc,
                                           uint64_t b_desc, uint32_t enable) {
    asm volatile(
        "{\n\t.reg .pred p;\n\t"
        "setp.ne.u32 p, %4, 0;\n\t"
        "tcgen05.mma.cta_group::1.kind::f16 [%0], %1, %2, %3, {%5, %5, %5, %5}, p;\n\t}"
        :: "r"(d_tmem), "l"(a_desc), "l"(b_desc), "r"(IDESC_F16),
           "r"(enable), "r"(0u)
        : "memory");
}
#endif // HAS_TCGEN05

__device__ __forceinline__ uint32_t swz(uint32_t off) {   // SW128 swizzle
    return off ^ ((off >> 3) & 0x70);
}

// SMEM layout (dynamic): [0]=tmem ptr, [16],[24]=mbar0/1, tiles 1024-aligned
#define SM_TMEMPTR 0
#define SM_MBAR0   16
#define SM_MBAR1   24
#define SM_A0      1024
#define SM_A1      (SM_A0 + BM * 128)            // A tile = 16KB
#define SM_B0      (SM_A1 + BM * 128)
#define SM_B1      (SM_B0 + BN * 128)            // B tile = 32KB
#define SM_TOTAL   (SM_B1 + BN * 128)            // 99328

// ---------------------------------------------------------------------------
// fp16 NT GEMM on tcgen05:  C[m][n] = alpha * sum_k A[m][k] * B[n][k]
// A: [M,K] fp16 rm (rows by*128), B: [N,K] fp16 rm (rows bx*256).
// C: fp32 [M,ldc] if !outHalf else fp16 [M,ldc]. K multiple of 64.
// ---------------------------------------------------------------------------
__global__ void __launch_bounds__(256)
gemm_nt_f16(const __half* __restrict__ A, const __half* __restrict__ B,
            void* __restrict__ Cv, int K, int ldc,
            long long sA, long long sB, long long sC, float alpha, int outHalf)
{
    const int tid = threadIdx.x;

    A += (long long)blockIdx.z * sA + (long long)blockIdx.y * BM * K;
    B += (long long)blockIdx.z * sB + (long long)blockIdx.x * BN * K;
    const long long cOff = (long long)blockIdx.z * sC
                         + (long long)blockIdx.y * BM * ldc
                         + (long long)blockIdx.x * BN;

#if HAS_TCGEN05
    extern __shared__ char smem[];
    const uint32_t sbase = smem_u32(smem);
    const int wid = tid >> 5;
    const int lid = tid & 31;

    if (wid == 0) {
        TCG_ALLOC(sbase + SM_TMEMPTR, 256);
        TCG_RELINQ();
    }
    if (tid == 0) {
        MBAR_INIT(sbase + SM_MBAR0, 1);
        MBAR_INIT(sbase + SM_MBAR1, 1);
    }
    __syncthreads();
    uint32_t tmem;
    asm volatile("ld.shared.b32 %0, [%1];" : "=r"(tmem) : "r"(sbase + SM_TMEMPTR));

    const int KT = K / BK;
    // loaders: 8 lanes per 128B row (16B each), rows step by 32
    const int lrow = tid >> 3;
    const int lcolB = (tid & 7) * 16;        // byte offset in row
    const int lcolE = (tid & 7) * 8;         // fp16 element offset

    for (int ic = 0; ic < KT; ic++) {
        const int buf = ic & 1;
        const int use = ic >> 1;
        const uint32_t mbar = sbase + (buf ? SM_MBAR1 : SM_MBAR0);
        if (use > 0) { MBAR_WAIT(mbar, (use - 1) & 1); }

        const uint32_t aBase = sbase + (buf ? SM_A1 : SM_A0);
        const uint32_t bBase = sbase + (buf ? SM_B1 : SM_B0);
        const long long k0 = (long long)ic * BK;

        #pragma unroll
        for (int p = 0; p < BM / 32; p++) {
            const int r = lrow + p * 32;
            const uint4 v = *reinterpret_cast<const uint4*>(A + (long long)r * K + k0 + lcolE);
            const uint32_t a = aBase + swz((uint32_t)(r * 128 + lcolB));
            asm volatile("st.shared.v4.b32 [%0], {%1,%2,%3,%4};"
                         :: "r"(a), "r"(v.x), "r"(v.y), "r"(v.z), "r"(v.w) : "memory");
        }
        #pragma unroll
        for (int p = 0; p < BN / 32; p++) {
            const int r = lrow + p * 32;
            const uint4 v = *reinterpret_cast<const uint4*>(B + (long long)r * K + k0 + lcolE);
            const uint32_t a = bBase + swz((uint32_t)(r * 128 + lcolB));
            asm volatile("st.shared.v4.b32 [%0], {%1,%2,%3,%4};"
                         :: "r"(a), "r"(v.x), "r"(v.y), "r"(v.z), "r"(v.w) : "memory");
        }
        FENCE_ASYNC_SHARED();
        __syncthreads();

        if (wid == 0) {
            if (elect_one()) {
                const uint64_t ad = make_desc(aBase);
                const uint64_t bd = make_desc(bBase);
                #pragma unroll
                for (int s = 0; s < 4; s++) {   // 4 x K=16 fp16 steps per 128B row
                    mma_f16_ss(tmem, ad + s * 2, bd + s * 2,
                               (ic > 0 || s > 0) ? 1u : 0u);
                }
                TCG_COMMIT(mbar);
            }
        }
    }

    {
        const int lastBuf = (KT - 1) & 1;
        const int cnt = (KT + 1) >> 1;
        const uint32_t mbar = sbase + (lastBuf ? SM_MBAR1 : SM_MBAR0);
        MBAR_WAIT(mbar, (cnt - 1) & 1);
    }
    TCG_FENCE_AFTER();

    // Epilogue: 8 warps; rows (wid&3)*32+lid, col half (wid>>2)*128
    {
        const int m = (wid & 3) * 32 + lid;
        const int chalf = (wid >> 2) * 128;
        #pragma unroll
        for (int j = 0; j < 4; j++) {
            uint32_t r[32];
            TCG_LD_X32(r, tmem + chalf + j * 32);
            TCG_WAIT_LD();
            float f[32];
            #pragma unroll
            for (int c = 0; c < 32; c++) f[c] = __uint_as_float(r[c]) * alpha;
            if (!outHalf) {
                float* crow = (float*)Cv + cOff + (long long)m * ldc + chalf + j * 32;
                #pragma unroll
                for (int c = 0; c < 8; c++)
                    *reinterpret_cast<float4*>(crow + c * 4) =
                        *reinterpret_cast<float4*>(&f[c * 4]);
            } else {
                __half* crow = (__half*)Cv + cOff + (long long)m * ldc + chalf + j * 32;
                uint32_t h[16];
                #pragma unroll
                for (int c = 0; c < 16; c++) {
                    __half2 p = __floats2half2_rn(f[c * 2], f[c * 2 + 1]);
                    h[c] = *reinterpret_cast<uint32_t*>(&p);
                }
                #pragma unroll
                for (int c = 0; c < 4; c++) {
                    uint4 v = make_uint4(h[c * 4], h[c * 4 + 1], h[c * 4 + 2], h[c * 4 + 3]);
                    *reinterpret_cast<uint4*>(crow + c * 8) = v;
                }
            }
        }
    }
    TCG_FENCE_BEFORE();
    __syncthreads();
    if (wid == 0) TCG_DEALLOC(tmem, 256);

#else
    // Baseline-pass fallback (never selected at runtime on sm_103a).
    const int trow = (tid >> 4) * 8;
    const int tcol = (tid & 15) * 16;
    float acc[8][16];
    #pragma unroll
    for (int i = 0; i < 8; i++)
        #pragma unroll
        for (int j = 0; j < 16; j++) acc[i][j] = 0.f;
    for (int k = 0; k < K; k++) {
        float ar[8], br[16];
        #pragma unroll
        for (int i = 0; i < 8; i++) ar[i] = __half2float(A[(long long)(trow + i) * K + k]);
        #pragma unroll
        for (int j = 0; j < 16; j++) br[j] = __half2float(B[(long long)(tcol + j) * K + k]);
        #pragma unroll
        for (int i = 0; i < 8; i++)
            #pragma unroll
            for (int j = 0; j < 16; j++)
                acc[i][j] = fmaf(ar[i], br[j], acc[i][j]);
    }
    #pragma unroll
    for (int i = 0; i < 8; i++)
        #pragma unroll
        for (int j = 0; j < 16; j++) {
            const long long idx = cOff + (long long)(trow + i) * ldc + tcol + j;
            if (outHalf) ((__half*)Cv)[idx] = __float2half(acc[i][j] * alpha);
            else         ((float*)Cv)[idx] = acc[i][j] * alpha;
        }
#endif
}

// ---------------------------------------------------------------------------
// Elementwise fp32 -> fp16 convert
// ---------------------------------------------------------------------------
__global__ void __launch_bounds__(256)
cvt_f32_f16(const float* __restrict__ in, __half* __restrict__ out, long long n)
{
    const long long i = ((long long)blockIdx.x * 256 + threadIdx.x) * 4;
    if (i + 3 < n) {
        float4 v = *reinterpret_cast<const float4*>(in + i);
        __half2 a = __floats2half2_rn(v.x, v.y);
        __half2 b = __floats2half2_rn(v.z, v.w);
        uint32_t pa = *reinterpret_cast<uint32_t*>(&a);
        uint32_t pb = *reinterpret_cast<uint32_t*>(&b);
        *reinterpret_cast<uint2*>(out + i) = make_uint2(pa, pb);
    }
}

// ---------------------------------------------------------------------------
// Transpose fp32 -> fp16: out[c][r] = (half) in[r][c]
// ---------------------------------------------------------------------------
__global__ void __launch_bounds__(256)
transpose_f32_to_f16(const float* __restrict__ in, __half* __restrict__ out,
                     int R, int C)
{
    __shared__ float t[32][33];
    const int c0 = blockIdx.x * 32, r0 = blockIdx.y * 32;
    #pragma unroll
    for (int i = threadIdx.y; i < 32; i += 8)
        t[i][threadIdx.x] = in[(long long)(r0 + i) * C + c0 + threadIdx.x];
    __syncthreads();
    #pragma unroll
    for (int i = threadIdx.y; i < 32; i += 8)
        out[(long long)(c0 + i) * R + r0 + threadIdx.x] = __float2half(t[threadIdx.x][i]);
}

// ---------------------------------------------------------------------------
// Transpose fp16: out[c][r] = in[r][c], per-batch strides
// ---------------------------------------------------------------------------
__global__ void __launch_bounds__(256)
transpose_f16(const __half* __restrict__ in, __half* __restrict__ out,
              int R, int C, long long sIn, long long sOut)
{
    __shared__ __half t[32][34];
    in  += (long long)blockIdx.z * sIn;
    out += (long long)blockIdx.z * sOut;
    const int c0 = blockIdx.x * 32, r0 = blockIdx.y * 32;
    #pragma unroll
    for (int i = threadIdx.y; i < 32; i += 8)
        t[i][threadIdx.x] = in[(long long)(r0 + i) * C + c0 + threadIdx.x];
    __syncthreads();
    #pragma unroll
    for (int i = threadIdx.y; i < 32; i += 8)
        out[(long long)(c0 + i) * R + r0 + threadIdx.x] = t[threadIdx.x][i];
}

// ---------------------------------------------------------------------------
// Row softmax in place (fp32) + fp16 copy. One block per row, 256 threads.
// ---------------------------------------------------------------------------
__inline__ __device__ float warpMax(float v) {
    #pragma unroll
    for (int o = 16; o > 0; o >>= 1) v = fmaxf(v, __shfl_xor_sync(0xffffffffu, v, o));
    return v;
}
__inline__ __device__ float warpSum(float v) {
    #pragma unroll
    for (int o = 16; o > 0; o >>= 1) v += __shfl_xor_sync(0xffffffffu, v, o);
    return v;
}

__global__ void __launch_bounds__(256)
softmax_rows(float* __restrict__ W, __half* __restrict__ WH)
{
    float* row = W + (long long)blockIdx.x * SS;
    __half* hrow = WH + (long long)blockIdx.x * SS;
    const int tid = threadIdx.x;
    __shared__ float red[8];

    float v[8];
    float m = -INFINITY;
    #pragma unroll
    for (int i = 0; i < 8; i++) {
        v[i] = row[tid + i * 256];
        m = fmaxf(m, v[i]);
    }
    m = warpMax(m);
    if ((tid & 31) == 0) red[tid >> 5] = m;
    __syncthreads();
    if (tid < 32) {
        float t = (tid < 8) ? red[tid] : -INFINITY;
        t = warpMax(t);
        if (tid == 0) red[0] = t;
    }
    __syncthreads();
    m = red[0];

    float s = 0.f;
    #pragma unroll
    for (int i = 0; i < 8; i++) {
        v[i] = __expf(v[i] - m);
        s += v[i];
    }
    s = warpSum(s);
    __syncthreads();
    if ((tid & 31) == 0) red[tid >> 5] = s;
    __syncthreads();
    if (tid < 32) {
        float t = (tid < 8) ? red[tid] : 0.f;
        t = warpSum(t);
        if (tid == 0) red[0] = t;
    }
    __syncthreads();
    const float inv = 1.0f / red[0];

    #pragma unroll
    for (int i = 0; i < 8; i++) {
        const float o = v[i] * inv;
        row[tid + i * 256] = o;
        hrow[tid + i * 256] = __float2half(o);
    }
}

// ---------------------------------------------------------------------------
// kernel_launch
// d_in: 0=input [B,S,D], 1=context [B,S,D], 2=Wq, 3=Wk, 4=Wv, 5=Wo ([D,D])
// d_out: output [B,S,D] then weights [B,S,S], fp32.
// ---------------------------------------------------------------------------
extern "C" void kernel_launch(void* const* d_in, const int* in_sizes, int n_in,
                              void* d_out, int out_size)
{
    const float* input   = (const float*)d_in[0];
    const float* context = (const float*)d_in[1];
    const float* Wq      = (const float*)d_in[2];
    const float* Wk      = (const float*)d_in[3];
    const float* Wv      = (const float*)d_in[4];
    const float* Wo      = (const float*)d_in[5];

    float* out     = (float*)d_out;                          // [B,S,D]
    float* weights = out + (long long)BB * SS * DD;          // [B,S,S]

    __half *xh, *ch, *wth, *qh, *kh, *vh, *vth, *wh, *ctxh;
    cudaGetSymbolAddress((void**)&xh,   g_XH);
    cudaGetSymbolAddress((void**)&ch,   g_CH);
    cudaGetSymbolAddress((void**)&wth,  g_WTH);
    cudaGetSymbolAddress((void**)&qh,   g_QH);
    cudaGetSymbolAddress((void**)&kh,   g_KH);
    cudaGetSymbolAddress((void**)&vh,   g_VH);
    cudaGetSymbolAddress((void**)&vth,  g_VTH);
    cudaGetSymbolAddress((void**)&wh,   g_WH);
    cudaGetSymbolAddress((void**)&ctxh, g_CTXH);
    __half* WqT = wth;
    __half* WkT = wth + 1 * DD * DD;
    __half* WvT = wth + 2 * DD * DD;
    __half* WoT = wth + 3 * DD * DD;

    cudaFuncSetAttribute(gemm_nt_f16,
                         cudaFuncAttributeMaxDynamicSharedMemorySize, SM_TOTAL);

    const dim3 blk(256);
    const dim3 tblk(32, 8);
    const long long SD  = (long long)SS * DD;
    const long long SSq = (long long)SS * SS;
    const long long NX  = (long long)BB * SS * DD;

    // 0) Convert inputs + transposed weights to fp16 (once per launch)
    cvt_f32_f16<<<(unsigned)((NX / 4 + 255) / 256), blk>>>(input,   xh, NX);
    cvt_f32_f16<<<(unsigned)((NX / 4 + 255) / 256), blk>>>(context, ch, NX);
    {
        dim3 g(DD / 32, DD / 32, 1);
        transpose_f32_to_f16<<<g, tblk>>>(Wq, WqT, DD, DD);
        transpose_f32_to_f16<<<g, tblk>>>(Wk, WkT, DD, DD);
        transpose_f32_to_f16<<<g, tblk>>>(Wv, WvT, DD, DD);
        transpose_f32_to_f16<<<g, tblk>>>(Wo, WoT, DD, DD);
    }

    // 1) Projections (fp16 out): [B*S, D] @ W == NT with W^T
    {
        dim3 g(DD / BN, (BB * SS) / BM, 1);
        gemm_nt_f16<<<g, blk, SM_TOTAL>>>(xh, WqT, qh, DD, DD, 0, 0, 0, 1.0f, 1);
        gemm_nt_f16<<<g, blk, SM_TOTAL>>>(ch, WkT, kh, DD, DD, 0, 0, 0, 1.0f, 1);
        gemm_nt_f16<<<g, blk, SM_TOTAL>>>(ch, WvT, vh, DD, DD, 0, 0, 0, 1.0f, 1);
    }

    // 1b) V^T per batch: [S,D] -> [D,S] (fp16)
    {
        dim3 g(DD / 32, SS / 32, BB);
        transpose_f16<<<g, tblk>>>(vh, vth, SS, DD, SD, SD);
    }

    // 2) scores = Q @ K^T * (1/sqrt(D)) -> weights slice (fp32 out)
    {
        dim3 g(SS / BN, SS / BM, BB);
        gemm_nt_f16<<<g, blk, SM_TOTAL>>>(qh, kh, weights, DD, SS, SD, SD, SSq, 0.03125f, 0);
    }

    // 3) softmax in place (fp32) + fp16 copy
    softmax_rows<<<BB * SS, blk>>>(weights, wh);

    // 4) ctx = weights @ V == NT with V^T (fp16 out)
    {
        dim3 g(DD / BN, SS / BM, BB);
        gemm_nt_f16<<<g, blk, SM_TOTAL>>>(wh, vth, ctxh, SS, DD, SSq, SD, SD, 1.0f, 1);
    }

    // 5) output = ctx @ Wo == NT with Wo^T (fp32 out)
    {
        dim3 g(DD / BN, (BB * SS) / BM, 1);
        gemm_nt_f16<<<g, blk, SM_TOTAL>>>(ctxh, WoT, out, DD, DD, 0, 0, 0, 1.0f, 0);
    }
}